// round 15
// baseline (speedup 1.0000x reference)
#include <cuda_runtime.h>
#include <cuda_bf16.h>
#include <cuda_fp16.h>
#include <stdint.h>
#include <math.h>

#define B_ 64
#define T_ 512
#define I_ 256
#define H_ 1024
#define G_ 4096
#define O_ 256

// ---------------- device scratch ----------------
__device__ float g_xproj0[(size_t)T_ * B_ * G_];   // [t][b][4H] fp32 (layer0 input proj)
__device__ __nv_bfloat16 g_xhi[(size_t)B_ * T_ * I_];
__device__ __nv_bfloat16 g_xlo[(size_t)B_ * T_ * I_];
__device__ __nv_bfloat16 g_wih0hi[(size_t)G_ * I_];
__device__ __nv_bfloat16 g_wih0lo[(size_t)G_ * I_];
__device__ __half g_wi1h[(size_t)G_ * H_];         // W_ih1 fp16 [4H][H]
__device__ __half g_wh1h[(size_t)G_ * H_];         // W_hh1 fp16 [4H][H]
__device__ __half g_h0[2][B_ * H_];                // layer0 h, fp16, double buffer
__device__ __half g_h1[2][B_ * H_];                // layer1 h
__device__ float g_hlast[B_ * H_];                 // fp32 final h1 for FC
__device__ unsigned int g_cnt[8 * 32];             // 8 group counters, 128B padded
__device__ unsigned int g_super;

// ---------------- helpers ----------------
__device__ __forceinline__ void ldsm4(uint32_t* r, uint32_t addr) {
    asm volatile("ldmatrix.sync.aligned.m8n8.x4.shared.b16 {%0,%1,%2,%3}, [%4];"
        : "=r"(r[0]), "=r"(r[1]), "=r"(r[2]), "=r"(r[3]) : "r"(addr));
}
__device__ __forceinline__ void ldsm2(uint32_t* r, uint32_t addr) {
    asm volatile("ldmatrix.sync.aligned.m8n8.x2.shared.b16 {%0,%1}, [%2];"
        : "=r"(r[0]), "=r"(r[1]) : "r"(addr));
}
__device__ __forceinline__ void mma16816(float* c, const uint32_t* a, const uint32_t* b) {
    asm volatile("mma.sync.aligned.m16n8k16.row.col.f32.bf16.bf16.f32 "
        "{%0,%1,%2,%3}, {%4,%5,%6,%7}, {%8,%9}, {%0,%1,%2,%3};"
        : "+f"(c[0]), "+f"(c[1]), "+f"(c[2]), "+f"(c[3])
        : "r"(a[0]), "r"(a[1]), "r"(a[2]), "r"(a[3]), "r"(b[0]), "r"(b[1]));
}
__device__ __forceinline__ void mma16816h(float* c, const uint32_t* a, const uint32_t* b) {
    asm volatile("mma.sync.aligned.m16n8k16.row.col.f32.f16.f16.f32 "
        "{%0,%1,%2,%3}, {%4,%5,%6,%7}, {%8,%9}, {%0,%1,%2,%3};"
        : "+f"(c[0]), "+f"(c[1]), "+f"(c[2]), "+f"(c[3])
        : "r"(a[0]), "r"(a[1]), "r"(a[2]), "r"(a[3]), "r"(b[0]), "r"(b[1]));
}
__device__ __forceinline__ uint32_t cvta_s(const void* p) {
    return (uint32_t)__cvta_generic_to_shared(p);
}
__device__ __forceinline__ unsigned int ld_acq(const unsigned int* p) {
    unsigned int v;
    asm volatile("ld.acquire.gpu.u32 %0, [%1];" : "=r"(v) : "l"(p) : "memory");
    return v;
}
__device__ __forceinline__ float fsigmoid(float x) {
    return __fdividef(1.f, 1.f + __expf(-x));
}
__device__ __forceinline__ float ftanh(float x) {
    return 1.f - __fdividef(2.f, 1.f + __expf(2.f * x));
}
#define CP_ASYNC16(d, s) asm volatile("cp.async.cg.shared.global [%0], [%1], 16;" :: "r"(d), "l"(s))
#define CP_COMMIT()      asm volatile("cp.async.commit_group;" ::: "memory")
#define CP_WAIT0()       asm volatile("cp.async.wait_group 0;" ::: "memory")

// ---------------- init ----------------
__global__ void init_kernel() {
    int idx = blockIdx.x * blockDim.x + threadIdx.x;
    if (idx < 8 * 32) g_cnt[idx] = 0u;
    if (idx == 0) g_super = 0u;
    __half z = __float2half(0.f);
    int n = 2 * B_ * H_;
    __half* p0 = (__half*)g_h0;
    __half* p1 = (__half*)g_h1;
    for (int i = idx; i < n; i += gridDim.x * blockDim.x) { p0[i] = z; p1[i] = z; }
}

// ---------------- fp32 -> bf16 hi/lo split ----------------
__global__ void split_kernel(const float* __restrict__ src,
                             __nv_bfloat16* __restrict__ hi,
                             __nv_bfloat16* __restrict__ lo, int n4) {
    int i = blockIdx.x * blockDim.x + threadIdx.x;
    if (i >= n4) return;
    float4 v = ((const float4*)src)[i];
    __nv_bfloat16 h0 = __float2bfloat16(v.x);
    __nv_bfloat16 h1 = __float2bfloat16(v.y);
    __nv_bfloat16 h2 = __float2bfloat16(v.z);
    __nv_bfloat16 h3 = __float2bfloat16(v.w);
    __nv_bfloat162 a, b;
    a.x = h0; a.y = h1; b.x = h2; b.y = h3;
    ((__nv_bfloat162*)hi)[2 * i] = a;
    ((__nv_bfloat162*)hi)[2 * i + 1] = b;
    a.x = __float2bfloat16(v.x - __bfloat162float(h0));
    a.y = __float2bfloat16(v.y - __bfloat162float(h1));
    b.x = __float2bfloat16(v.z - __bfloat162float(h2));
    b.y = __float2bfloat16(v.w - __bfloat162float(h3));
    ((__nv_bfloat162*)lo)[2 * i] = a;
    ((__nv_bfloat162*)lo)[2 * i + 1] = b;
}

// ---------------- fp32 -> fp16 convert ----------------
__global__ void conv_half(const float* __restrict__ src, __half* __restrict__ dst, int n4) {
    int i = blockIdx.x * blockDim.x + threadIdx.x;
    if (i >= n4) return;
    float4 v = ((const float4*)src)[i];
    __half2 a, b;
    a.x = __float2half(v.x); a.y = __float2half(v.y);
    b.x = __float2half(v.z); b.y = __float2half(v.w);
    ((__half2*)dst)[2 * i] = a;
    ((__half2*)dst)[2 * i + 1] = b;
}

// ---------------- hierarchical grid barrier ----------------
__device__ __forceinline__ void gridbar2(int t, int bid) {
    __threadfence();
    __syncthreads();
    if (threadIdx.x == 0) {
        unsigned int r = atomicAdd(&g_cnt[(bid >> 4) * 32], 1u);
        if ((r & 15u) == 15u) atomicAdd(&g_super, 1u);
        unsigned int tgt = 8u * (unsigned int)(t + 1);
        while (ld_acq(&g_super) < tgt) __nanosleep(32);
    }
    __syncthreads();
}

// ---------------- split-bf16 MMA projection GEMM (layer0 only) --------------
#define P_ASZ (128 * 40)
#define P_BSZ (64 * 40)
#define P_BUF (2 * P_ASZ + 2 * P_BSZ)
__global__ __launch_bounds__(256) void mma_xproj(
    const __nv_bfloat16* __restrict__ Ahi, const __nv_bfloat16* __restrict__ Alo,
    const __nv_bfloat16* __restrict__ Whi, const __nv_bfloat16* __restrict__ Wlo,
    const float* __restrict__ b1, const float* __restrict__ b2,
    float* __restrict__ Cout, int K)
{
    extern __shared__ __nv_bfloat16 psm[];
    __shared__ float sBias[64];

    int tid = threadIdx.x;
    int n0 = blockIdx.x * 64;
    int m0 = blockIdx.y * 128;
    int w = tid >> 5, lane = tid & 31;
    int r0 = w * 16;

    if (tid < 64) sBias[tid] = b1[n0 + tid] + b2[n0 + tid];

    float acc[8][4];
#pragma unroll
    for (int i = 0; i < 8; i++)
#pragma unroll
        for (int j = 0; j < 4; j++) acc[i][j] = 0.f;

    size_t arow[2]; int aoff[2];
#pragma unroll
    for (int it = 0; it < 2; it++) {
        int idx = tid + it * 256;
        int r = idx >> 2, seg = idx & 3;
        int m = m0 + r;
        arow[it] = ((size_t)(m & 63) * T_ + (size_t)(m >> 6)) * (size_t)K + (size_t)(seg * 8);
        aoff[it] = r * 40 + seg * 8;
    }
    int br = tid >> 2, bseg = tid & 3;
    size_t brow = (size_t)(n0 + br) * (size_t)K + (size_t)(bseg * 8);
    int boff = br * 40 + bseg * 8;

    int lrA = (lane & 7) + (lane & 8);
    int lcA = (lane & 16) ? 8 : 0;
    int lrB = lane & 7;
    int lcB = (lane & 8) ? 8 : 0;

    uint32_t dAhi[2], dAlo[2], dBhi[2], dBlo[2];
    uint32_t aHiB[2], aLoB[2], bHiB[2], bLoB[2];
#pragma unroll
    for (int buf = 0; buf < 2; buf++) {
        uint32_t base = cvta_s(psm + buf * P_BUF);
        dAhi[buf] = base;
        dAlo[buf] = base + P_ASZ * 2;
        dBhi[buf] = base + 2 * P_ASZ * 2;
        dBlo[buf] = base + (2 * P_ASZ + P_BSZ) * 2;
        aHiB[buf] = dAhi[buf] + (uint32_t)(((r0 + lrA) * 40 + lcA) * 2);
        aLoB[buf] = dAlo[buf] + (uint32_t)(((r0 + lrA) * 40 + lcA) * 2);
        bHiB[buf] = dBhi[buf] + (uint32_t)((lrB * 40 + lcB) * 2);
        bLoB[buf] = dBlo[buf] + (uint32_t)((lrB * 40 + lcB) * 2);
    }

#define PREFP(kc, buf) do {                                                   \
    _Pragma("unroll")                                                         \
    for (int it = 0; it < 2; it++) {                                          \
        CP_ASYNC16(dAhi[(buf)] + (uint32_t)(aoff[it] * 2), Ahi + arow[it] + (kc)); \
        CP_ASYNC16(dAlo[(buf)] + (uint32_t)(aoff[it] * 2), Alo + arow[it] + (kc)); \
    }                                                                         \
    CP_ASYNC16(dBhi[(buf)] + (uint32_t)(boff * 2), Whi + brow + (kc));        \
    CP_ASYNC16(dBlo[(buf)] + (uint32_t)(boff * 2), Wlo + brow + (kc));        \
    CP_COMMIT();                                                              \
} while (0)

    PREFP(0, 0);

    for (int kc = 0; kc < K; kc += 32) {
        int buf = (kc >> 5) & 1;
        CP_WAIT0();
        __syncthreads();
        if (kc + 32 < K) PREFP(kc + 32, buf ^ 1);
#pragma unroll
        for (int ks = 0; ks < 2; ks++) {
            int k0 = ks * 16;
            uint32_t ah[4], al[4];
            ldsm4(ah, aHiB[buf] + (uint32_t)(k0 * 2));
            ldsm4(al, aLoB[buf] + (uint32_t)(k0 * 2));
#pragma unroll
            for (int nt = 0; nt < 8; nt++) {
                uint32_t bh[2], bl[2];
                uint32_t off = (uint32_t)(nt * 8 * 40 + k0) * 2u;
                ldsm2(bh, bHiB[buf] + off);
                ldsm2(bl, bLoB[buf] + off);
                mma16816(acc[nt], ah, bh);
                mma16816(acc[nt], ah, bl);
                mma16816(acc[nt], al, bh);
            }
        }
        __syncthreads();
    }
#undef PREFP

    int g = lane >> 2, tq = lane & 3;
#pragma unroll
    for (int nt = 0; nt < 8; nt++) {
        int col = nt * 8 + tq * 2;
        float bb0 = sBias[col], bb1 = sBias[col + 1];
        size_t mA = (size_t)(m0 + r0 + g) * G_ + n0 + col;
        size_t mB = (size_t)(m0 + r0 + g + 8) * G_ + n0 + col;
        float2 v0 = make_float2(acc[nt][0] + bb0, acc[nt][1] + bb1);
        float2 v1 = make_float2(acc[nt][2] + bb0, acc[nt][3] + bb1);
        *(float2*)&Cout[mA] = v0;
        *(float2*)&Cout[mB] = v1;
    }
}
#define SMEM_PROJ (P_BUF * 2 * 2)

// ---------------- FUSED 2-layer LSTM recurrence (balanced) ------------------
// 128 blocks x 512 threads, 513 fused steps. Block bid owns h0/h1 cols
// [8bid, 8bid+8). 12 col-tiles of 8 gate-cols: tiles 0-3 = W_hh0 (resident,
// A=h0), tiles 4-7 = W_ih1 (streamed, A=h0), tiles 8-11 = W_hh1 (streamed,
// A=h1). Warp w: rowg=w&3, colg=w>>2; colg c owns tiles {3c,3c+1,3c+2}
// -> 24 MMA/warp/chunk, balanced.
extern __shared__ char smem_dyn[];
__global__ __launch_bounds__(512) void lstm_fused(
    const float* __restrict__ xproj,
    const float* __restrict__ Whh0,
    const float* __restrict__ bih1, const float* __restrict__ bhh1)
{
    __half* sW0 = (__half*)smem_dyn;            // 32 x 1032 resident
    __half* sH0 = sW0 + 32 * 1032;              // 2 x 64x136
    __half* sH1 = sH0 + 2 * 8704;               // 2 x 64x136
    __half* sWi = sH1 + 2 * 8704;               // 2 x 32x136 (W_ih1 stream)
    __half* sW1 = sWi + 2 * 4352;               // 2 x 32x136 (W_hh1 stream)
    float* sG01 = (float*)(sW1 + 2 * 4352);     // 64 x 66
    float* sG1  = sG01 + 64 * 66;               // 64 x 34
    float* sC0  = sG1 + 64 * 34;                // 512
    float* sC1  = sC0 + 512;                    // 512
    float* sB1  = sC1 + 512;                    // 32

    int tid = threadIdx.x, w = tid >> 5, lane = tid & 31;
    int bid = blockIdx.x;
    int jbase = bid * 8;

    for (int i = tid; i < 32 * 1024; i += 512) {
        int n = i >> 10, k = i & 1023;
        float v = Whh0[(size_t)((n >> 3) * H_ + jbase + (n & 7)) * H_ + k];
        sW0[n * 1032 + k] = __float2half(v);
    }
    if (tid < 32) {
        int gr = (tid >> 3) * H_ + jbase + (tid & 7);
        sB1[tid] = bih1[gr] + bhh1[gr];
    }
    sC0[tid] = 0.f;
    sC1[tid] = 0.f;

    int rowg = w & 3, colg = w >> 2;             // colg 0..3
    int r0 = rowg * 16;
    int lrA = (lane & 7) + (lane & 8);
    int lcA = (lane & 16) ? 8 : 0;
    int bRow = lane & 7;
    int bK = ((lane >> 3) & 3) * 8;

    // A-frag bases per buffer for both h0 and h1
    uint32_t aH0[2], aH1[2];
#pragma unroll
    for (int bf = 0; bf < 2; bf++) {
        aH0[bf] = cvta_s(&sH0[bf * 8704 + (r0 + lrA) * 136 + lcA]);
        aH1[bf] = cvta_s(&sH1[bf * 8704 + (r0 + lrA) * 136 + lcA]);
    }
    int needH0 = (colg < 3);                     // tiles < 8 present
    int needH1 = (colg >= 2);                    // tiles >= 8 present

    // B bases for this warp's 3 tiles
    int tis[3];
    int isRes[3];
    uint32_t bR[3], bS[2][3];
#pragma unroll
    for (int i = 0; i < 3; i++) {
        int ti = colg * 3 + i;
        tis[i] = ti;
        if (ti < 4) {
            isRes[i] = 1;
            bR[i] = cvta_s(&sW0[(ti * 8 + bRow) * 1032 + bK]);
            bS[0][i] = bS[1][i] = 0u;
        } else if (ti < 8) {
            isRes[i] = 0;
            bR[i] = 0u;
#pragma unroll
            for (int bf = 0; bf < 2; bf++)
                bS[bf][i] = cvta_s(&sWi[bf * 4352 + ((ti - 4) * 8 + bRow) * 136 + bK]);
        } else {
            isRes[i] = 0;
            bR[i] = 0u;
#pragma unroll
            for (int bf = 0; bf < 2; bf++)
                bS[bf][i] = cvta_s(&sW1[bf * 4352 + ((ti - 8) * 8 + bRow) * 136 + bK]);
        }
    }

    // cp.async destinations
    uint32_t dH0[2], dH1[2], dWi[2], dW1[2];
#pragma unroll
    for (int bf = 0; bf < 2; bf++) {
        dH0[bf] = cvta_s(&sH0[bf * 8704]);
        dH1[bf] = cvta_s(&sH1[bf * 8704]);
        dWi[bf] = cvta_s(&sWi[bf * 4352]);
        dW1[bf] = cvta_s(&sW1[bf * 4352]);
    }
    int pr[2], ps[2];
#pragma unroll
    for (int it = 0; it < 2; it++) {
        int idx = tid + it * 512;
        pr[it] = idx >> 4;
        ps[it] = (idx & 15) * 8;
    }
    int wrow = tid >> 4;
    int wseg = (tid & 15) * 8;
    uint32_t wso = (uint32_t)(wrow * 136 + wseg) * 2u;
    size_t wgrow = (size_t)((wrow >> 3) * H_ + jbase + (wrow & 7)) * (size_t)H_;
    const __half* gWi = g_wi1h;
    const __half* gW1 = g_wh1h;

    int g = lane >> 2, tq = lane & 3;
    int bA = r0 + g, bB = bA + 8;

    int cb = tid >> 3, cj = tid & 7;
    const float* xpb = xproj + (size_t)cb * G_ + jbase + cj;

    __syncthreads();

#define PREF(ch, bf) do {                                                     \
    int kc_ = (ch) * 128;                                                     \
    _Pragma("unroll")                                                         \
    for (int it = 0; it < 2; it++) {                                          \
        uint32_t so = (uint32_t)(pr[it] * 136 + ps[it]) * 2u;                 \
        CP_ASYNC16(dH0[(bf)] + so, hr0 + pr[it] * H_ + kc_ + ps[it]);         \
        CP_ASYNC16(dH1[(bf)] + so, hr1 + pr[it] * H_ + kc_ + ps[it]);         \
    }                                                                         \
    CP_ASYNC16(dWi[(bf)] + wso, gWi + wgrow + kc_ + wseg);                    \
    CP_ASYNC16(dW1[(bf)] + wso, gW1 + wgrow + kc_ + wseg);                    \
    CP_COMMIT();                                                              \
} while (0)

    for (int t = 0; t <= T_; t++) {
        const __half* hr0 = g_h0[(t + 1) & 1];   // h0[t-1]
        const __half* hr1 = g_h1[t & 1];         // h1[t-2]

        PREF(0, 0);

        float xg0 = 0.f, xg1 = 0.f, xg2 = 0.f, xg3 = 0.f;
        if (t < T_) {
            size_t xt = (size_t)t * B_ * G_;
            xg0 = xpb[xt];
            xg1 = xpb[xt + 1 * H_];
            xg2 = xpb[xt + 2 * H_];
            xg3 = xpb[xt + 3 * H_];
        }

        float acc[3][4];
#pragma unroll
        for (int i = 0; i < 3; i++)
#pragma unroll
            for (int j = 0; j < 4; j++) acc[i][j] = 0.f;

        for (int ch = 0; ch < 8; ch++) {
            int cur = ch & 1;
            CP_WAIT0();
            __syncthreads();
            if (ch < 7) PREF(ch + 1, cur ^ 1);

            int kc = ch * 128;
#pragma unroll
            for (int kg = 0; kg < 4; kg++) {
                uint32_t koff = (uint32_t)(kg * 32) * 2u;
                uint32_t a0h0[4], a1h0[4], a0h1[4], a1h1[4];
                if (needH0) {
                    ldsm4(a0h0, aH0[cur] + koff);
                    ldsm4(a1h0, aH0[cur] + koff + 32);
                }
                if (needH1) {
                    ldsm4(a0h1, aH1[cur] + koff);
                    ldsm4(a1h1, aH1[cur] + koff + 32);
                }
#pragma unroll
                for (int i = 0; i < 3; i++) {
                    uint32_t b[4];
                    uint32_t addr = isRes[i] ? (bR[i] + (uint32_t)(kc + kg * 32) * 2u)
                                             : (bS[cur][i] + koff);
                    ldsm4(b, addr);
                    if (tis[i] < 8) {
                        mma16816h(acc[i], a0h0, b);
                        mma16816h(acc[i], a1h0, b + 2);
                    } else {
                        mma16816h(acc[i], a0h1, b);
                        mma16816h(acc[i], a1h1, b + 2);
                    }
                }
            }
        }

        // gate writes: tiles 0-7 -> sG01 (cols 0-63), tiles 8-11 -> sG1
#pragma unroll
        for (int i = 0; i < 3; i++) {
            int ti = tis[i];
            if (ti < 8) {
                int col = ti * 8 + tq * 2;
                *(float2*)&sG01[bA * 66 + col] = make_float2(acc[i][0], acc[i][1]);
                *(float2*)&sG01[bB * 66 + col] = make_float2(acc[i][2], acc[i][3]);
            } else {
                int col = (ti - 8) * 8 + tq * 2;
                *(float2*)&sG1[bA * 34 + col] = make_float2(acc[i][0], acc[i][1]);
                *(float2*)&sG1[bB * 34 + col] = make_float2(acc[i][2], acc[i][3]);
            }
        }
        __syncthreads();

        __half* wr0 = g_h0[t & 1];
        __half* wr1 = g_h1[(t + 1) & 1];
        if (t < T_) {
            float iv = sG01[cb * 66 + cj]      + xg0;
            float fv = sG01[cb * 66 + 8 + cj]  + xg1;
            float gv = sG01[cb * 66 + 16 + cj] + xg2;
            float ov = sG01[cb * 66 + 24 + cj] + xg3;
            float ig = fsigmoid(iv), fg = fsigmoid(fv);
            float gg = ftanh(gv), og = fsigmoid(ov);
            float cc = fg * sC0[tid] + ig * gg;
            sC0[tid] = cc;
            float hh = og * ftanh(cc);
            wr0[cb * H_ + jbase + cj] = __float2half(hh);
        }
        if (t >= 1) {
            float iv = sG01[cb * 66 + 32 + cj]      + sG1[cb * 34 + cj]      + sB1[cj];
            float fv = sG01[cb * 66 + 32 + 8 + cj]  + sG1[cb * 34 + 8 + cj]  + sB1[8 + cj];
            float gv = sG01[cb * 66 + 32 + 16 + cj] + sG1[cb * 34 + 16 + cj] + sB1[16 + cj];
            float ov = sG01[cb * 66 + 32 + 24 + cj] + sG1[cb * 34 + 24 + cj] + sB1[24 + cj];
            float ig = fsigmoid(iv), fg = fsigmoid(fv);
            float gg = ftanh(gv), og = fsigmoid(ov);
            float cc = fg * sC1[tid] + ig * gg;
            sC1[tid] = cc;
            float hh = og * ftanh(cc);
            wr1[cb * H_ + jbase + cj] = __float2half(hh);
            if (t == T_) g_hlast[cb * H_ + jbase + cj] = hh;
        }
        if (t < T_) gridbar2(t, bid);
    }
#undef PREF
}
#define SMEM_FUSED ((32*1032 + 2*8704*2 + 2*4352*2) * 2 + (64*66 + 64*34 + 512 + 512 + 32) * 4)

// ---------------- FC head ----------------
__global__ __launch_bounds__(256) void fc_kernel(
    const float* __restrict__ fc_w, const float* __restrict__ fc_b,
    float* __restrict__ out)
{
    __shared__ float sh[H_];
    int b = blockIdx.x, tid = threadIdx.x;
    const float* hlast = g_hlast + (size_t)b * H_;
    for (int i = tid; i < H_; i += 256) sh[i] = hlast[i];
    __syncthreads();
    int o = tid;
    const float* wrow = fc_w + (size_t)o * H_;
    float acc = fc_b[o];
#pragma unroll 8
    for (int k = 0; k < H_; k++) acc += sh[k] * wrow[k];
    out[b * O_ + o] = acc;
}

// ---------------- launch ----------------
extern "C" void kernel_launch(void* const* d_in, const int* in_sizes, int n_in,
                              void* d_out, int out_size) {
    (void)in_sizes; (void)n_in; (void)out_size;
    const float* x     = (const float*)d_in[0];
    const float* W_ih0 = (const float*)d_in[1];
    const float* W_hh0 = (const float*)d_in[2];
    const float* b_ih0 = (const float*)d_in[3];
    const float* b_hh0 = (const float*)d_in[4];
    const float* W_ih1 = (const float*)d_in[5];
    const float* W_hh1 = (const float*)d_in[6];
    const float* b_ih1 = (const float*)d_in[7];
    const float* b_hh1 = (const float*)d_in[8];
    const float* fc_w  = (const float*)d_in[9];
    const float* fc_b  = (const float*)d_in[10];
    float* out = (float*)d_out;

    float* xp0;
    __nv_bfloat16 *xhi, *xlo, *w0hi, *w0lo;
    __half *wi1h, *wh1h;
    cudaGetSymbolAddress((void**)&xp0, g_xproj0);
    cudaGetSymbolAddress((void**)&xhi, g_xhi);
    cudaGetSymbolAddress((void**)&xlo, g_xlo);
    cudaGetSymbolAddress((void**)&w0hi, g_wih0hi);
    cudaGetSymbolAddress((void**)&w0lo, g_wih0lo);
    cudaGetSymbolAddress((void**)&wi1h, g_wi1h);
    cudaGetSymbolAddress((void**)&wh1h, g_wh1h);

    cudaFuncSetAttribute(lstm_fused,
        cudaFuncAttributeMaxDynamicSharedMemorySize, SMEM_FUSED);
    cudaFuncSetAttribute(mma_xproj,
        cudaFuncAttributeMaxDynamicSharedMemorySize, SMEM_PROJ);

    int nx4 = B_ * T_ * I_ / 4;
    split_kernel<<<(nx4 + 255) / 256, 256>>>(x, xhi, xlo, nx4);
    int nw04 = G_ * I_ / 4;
    split_kernel<<<(nw04 + 255) / 256, 256>>>(W_ih0, w0hi, w0lo, nw04);
    int nw14 = G_ * H_ / 4;
    conv_half<<<(nw14 + 255) / 256, 256>>>(W_ih1, wi1h, nw14);
    conv_half<<<(nw14 + 255) / 256, 256>>>(W_hh1, wh1h, nw14);

    dim3 pgrid(G_ / 64, (B_ * T_) / 128);
    mma_xproj<<<pgrid, 256, SMEM_PROJ>>>(xhi, xlo, w0hi, w0lo, b_ih0, b_hh0, xp0, I_);

    init_kernel<<<64, 256>>>();
    lstm_fused<<<128, 512, SMEM_FUSED>>>(xp0, W_hh0, b_ih1, b_hh1);

    fc_kernel<<<64, 256>>>(fc_w, fc_b, out);
}

// round 16
// speedup vs baseline: 1.4116x; 1.4116x over previous
#include <cuda_runtime.h>
#include <cuda_bf16.h>
#include <cuda_fp16.h>
#include <stdint.h>
#include <math.h>

#define B_ 64
#define T_ 512
#define I_ 256
#define H_ 1024
#define G_ 4096
#define O_ 256

// ---------------- device scratch ----------------
__device__ float g_xproj0[(size_t)T_ * B_ * G_];   // [t][b][4H] fp32 (layer0 input proj)
__device__ __nv_bfloat16 g_xhi[(size_t)B_ * T_ * I_];
__device__ __nv_bfloat16 g_xlo[(size_t)B_ * T_ * I_];
__device__ __nv_bfloat16 g_wih0hi[(size_t)G_ * I_];
__device__ __nv_bfloat16 g_wih0lo[(size_t)G_ * I_];
__device__ __half g_wi1h[(size_t)G_ * H_];         // W_ih1 fp16 [4H][H]
__device__ __half g_wh1h[(size_t)G_ * H_];         // W_hh1 fp16 [4H][H]
__device__ __half g_h0[2][B_ * H_];                // layer0 h, fp16, double buffer
__device__ __half g_h1[2][B_ * H_];                // layer1 h
__device__ float g_hlast[B_ * H_];                 // fp32 final h1 for FC
__device__ unsigned int g_cnt[8 * 32];             // 8 group counters, 128B padded

// ---------------- helpers ----------------
__device__ __forceinline__ void ldsm4(uint32_t* r, uint32_t addr) {
    asm volatile("ldmatrix.sync.aligned.m8n8.x4.shared.b16 {%0,%1,%2,%3}, [%4];"
        : "=r"(r[0]), "=r"(r[1]), "=r"(r[2]), "=r"(r[3]) : "r"(addr));
}
__device__ __forceinline__ void ldsm2(uint32_t* r, uint32_t addr) {
    asm volatile("ldmatrix.sync.aligned.m8n8.x2.shared.b16 {%0,%1}, [%2];"
        : "=r"(r[0]), "=r"(r[1]) : "r"(addr));
}
__device__ __forceinline__ void mma16816(float* c, const uint32_t* a, const uint32_t* b) {
    asm volatile("mma.sync.aligned.m16n8k16.row.col.f32.bf16.bf16.f32 "
        "{%0,%1,%2,%3}, {%4,%5,%6,%7}, {%8,%9}, {%0,%1,%2,%3};"
        : "+f"(c[0]), "+f"(c[1]), "+f"(c[2]), "+f"(c[3])
        : "r"(a[0]), "r"(a[1]), "r"(a[2]), "r"(a[3]), "r"(b[0]), "r"(b[1]));
}
__device__ __forceinline__ void mma16816h(float* c, const uint32_t* a, const uint32_t* b) {
    asm volatile("mma.sync.aligned.m16n8k16.row.col.f32.f16.f16.f32 "
        "{%0,%1,%2,%3}, {%4,%5,%6,%7}, {%8,%9}, {%0,%1,%2,%3};"
        : "+f"(c[0]), "+f"(c[1]), "+f"(c[2]), "+f"(c[3])
        : "r"(a[0]), "r"(a[1]), "r"(a[2]), "r"(a[3]), "r"(b[0]), "r"(b[1]));
}
__device__ __forceinline__ uint32_t cvta_s(const void* p) {
    return (uint32_t)__cvta_generic_to_shared(p);
}
__device__ __forceinline__ unsigned int ld_acq(const unsigned int* p) {
    unsigned int v;
    asm volatile("ld.acquire.gpu.u32 %0, [%1];" : "=r"(v) : "l"(p) : "memory");
    return v;
}
__device__ __forceinline__ float fsigmoid(float x) {
    return __fdividef(1.f, 1.f + __expf(-x));
}
__device__ __forceinline__ float ftanh(float x) {
    return 1.f - __fdividef(2.f, 1.f + __expf(2.f * x));
}
#define CP_ASYNC16(d, s) asm volatile("cp.async.cg.shared.global [%0], [%1], 16;" :: "r"(d), "l"(s))
#define CP_COMMIT()      asm volatile("cp.async.commit_group;" ::: "memory")
#define CP_WAIT0()       asm volatile("cp.async.wait_group 0;" ::: "memory")

// ---------------- init ----------------
__global__ void init_kernel() {
    int idx = blockIdx.x * blockDim.x + threadIdx.x;
    if (idx < 8 * 32) g_cnt[idx] = 0u;
    __half z = __float2half(0.f);
    int n = 2 * B_ * H_;
    __half* p0 = (__half*)g_h0;
    __half* p1 = (__half*)g_h1;
    for (int i = idx; i < n; i += gridDim.x * blockDim.x) { p0[i] = z; p1[i] = z; }
}

// ---------------- fp32 -> bf16 hi/lo split ----------------
__global__ void split_kernel(const float* __restrict__ src,
                             __nv_bfloat16* __restrict__ hi,
                             __nv_bfloat16* __restrict__ lo, int n4) {
    int i = blockIdx.x * blockDim.x + threadIdx.x;
    if (i >= n4) return;
    float4 v = ((const float4*)src)[i];
    __nv_bfloat16 h0 = __float2bfloat16(v.x);
    __nv_bfloat16 h1 = __float2bfloat16(v.y);
    __nv_bfloat16 h2 = __float2bfloat16(v.z);
    __nv_bfloat16 h3 = __float2bfloat16(v.w);
    __nv_bfloat162 a, b;
    a.x = h0; a.y = h1; b.x = h2; b.y = h3;
    ((__nv_bfloat162*)hi)[2 * i] = a;
    ((__nv_bfloat162*)hi)[2 * i + 1] = b;
    a.x = __float2bfloat16(v.x - __bfloat162float(h0));
    a.y = __float2bfloat16(v.y - __bfloat162float(h1));
    b.x = __float2bfloat16(v.z - __bfloat162float(h2));
    b.y = __float2bfloat16(v.w - __bfloat162float(h3));
    ((__nv_bfloat162*)lo)[2 * i] = a;
    ((__nv_bfloat162*)lo)[2 * i + 1] = b;
}

// ---------------- fp32 -> fp16 convert ----------------
__global__ void conv_half(const float* __restrict__ src, __half* __restrict__ dst, int n4) {
    int i = blockIdx.x * blockDim.x + threadIdx.x;
    if (i >= n4) return;
    float4 v = ((const float4*)src)[i];
    __half2 a, b;
    a.x = __float2half(v.x); a.y = __float2half(v.y);
    b.x = __float2half(v.z); b.y = __float2half(v.w);
    ((__half2*)dst)[2 * i] = a;
    ((__half2*)dst)[2 * i + 1] = b;
}

// ---------------- flattened grid barrier (8 parallel pollers) ----------------
__device__ __forceinline__ void gridbar2(int t, int bid) {
    __threadfence();
    __syncthreads();
    if (threadIdx.x == 0) atomicAdd(&g_cnt[(bid >> 4) * 32], 1u);
    if (threadIdx.x < 8) {
        unsigned int tgt = 16u * (unsigned int)(t + 1);
        while (ld_acq(&g_cnt[threadIdx.x * 32]) < tgt) __nanosleep(32);
    }
    __syncthreads();
}

// ---------------- split-bf16 MMA projection GEMM (layer0 only) --------------
#define P_ASZ (128 * 40)
#define P_BSZ (64 * 40)
#define P_BUF (2 * P_ASZ + 2 * P_BSZ)
__global__ __launch_bounds__(256) void mma_xproj(
    const __nv_bfloat16* __restrict__ Ahi, const __nv_bfloat16* __restrict__ Alo,
    const __nv_bfloat16* __restrict__ Whi, const __nv_bfloat16* __restrict__ Wlo,
    const float* __restrict__ b1, const float* __restrict__ b2,
    float* __restrict__ Cout, int K)
{
    extern __shared__ __nv_bfloat16 psm[];
    __shared__ float sBias[64];

    int tid = threadIdx.x;
    int n0 = blockIdx.x * 64;
    int m0 = blockIdx.y * 128;
    int w = tid >> 5, lane = tid & 31;
    int r0 = w * 16;

    if (tid < 64) sBias[tid] = b1[n0 + tid] + b2[n0 + tid];

    float acc[8][4];
#pragma unroll
    for (int i = 0; i < 8; i++)
#pragma unroll
        for (int j = 0; j < 4; j++) acc[i][j] = 0.f;

    size_t arow[2]; int aoff[2];
#pragma unroll
    for (int it = 0; it < 2; it++) {
        int idx = tid + it * 256;
        int r = idx >> 2, seg = idx & 3;
        int m = m0 + r;
        arow[it] = ((size_t)(m & 63) * T_ + (size_t)(m >> 6)) * (size_t)K + (size_t)(seg * 8);
        aoff[it] = r * 40 + seg * 8;
    }
    int br = tid >> 2, bseg = tid & 3;
    size_t brow = (size_t)(n0 + br) * (size_t)K + (size_t)(bseg * 8);
    int boff = br * 40 + bseg * 8;

    int lrA = (lane & 7) + (lane & 8);
    int lcA = (lane & 16) ? 8 : 0;
    int lrB = lane & 7;
    int lcB = (lane & 8) ? 8 : 0;

    uint32_t dAhi[2], dAlo[2], dBhi[2], dBlo[2];
    uint32_t aHiB[2], aLoB[2], bHiB[2], bLoB[2];
#pragma unroll
    for (int buf = 0; buf < 2; buf++) {
        uint32_t base = cvta_s(psm + buf * P_BUF);
        dAhi[buf] = base;
        dAlo[buf] = base + P_ASZ * 2;
        dBhi[buf] = base + 2 * P_ASZ * 2;
        dBlo[buf] = base + (2 * P_ASZ + P_BSZ) * 2;
        aHiB[buf] = dAhi[buf] + (uint32_t)(((r0 + lrA) * 40 + lcA) * 2);
        aLoB[buf] = dAlo[buf] + (uint32_t)(((r0 + lrA) * 40 + lcA) * 2);
        bHiB[buf] = dBhi[buf] + (uint32_t)((lrB * 40 + lcB) * 2);
        bLoB[buf] = dBlo[buf] + (uint32_t)((lrB * 40 + lcB) * 2);
    }

#define PREFP(kc, buf) do {                                                   \
    _Pragma("unroll")                                                         \
    for (int it = 0; it < 2; it++) {                                          \
        CP_ASYNC16(dAhi[(buf)] + (uint32_t)(aoff[it] * 2), Ahi + arow[it] + (kc)); \
        CP_ASYNC16(dAlo[(buf)] + (uint32_t)(aoff[it] * 2), Alo + arow[it] + (kc)); \
    }                                                                         \
    CP_ASYNC16(dBhi[(buf)] + (uint32_t)(boff * 2), Whi + brow + (kc));        \
    CP_ASYNC16(dBlo[(buf)] + (uint32_t)(boff * 2), Wlo + brow + (kc));        \
    CP_COMMIT();                                                              \
} while (0)

    PREFP(0, 0);

    for (int kc = 0; kc < K; kc += 32) {
        int buf = (kc >> 5) & 1;
        CP_WAIT0();
        __syncthreads();
        if (kc + 32 < K) PREFP(kc + 32, buf ^ 1);
#pragma unroll
        for (int ks = 0; ks < 2; ks++) {
            int k0 = ks * 16;
            uint32_t ah[4], al[4];
            ldsm4(ah, aHiB[buf] + (uint32_t)(k0 * 2));
            ldsm4(al, aLoB[buf] + (uint32_t)(k0 * 2));
#pragma unroll
            for (int nt = 0; nt < 8; nt++) {
                uint32_t bh[2], bl[2];
                uint32_t off = (uint32_t)(nt * 8 * 40 + k0) * 2u;
                ldsm2(bh, bHiB[buf] + off);
                ldsm2(bl, bLoB[buf] + off);
                mma16816(acc[nt], ah, bh);
                mma16816(acc[nt], ah, bl);
                mma16816(acc[nt], al, bh);
            }
        }
        __syncthreads();
    }
#undef PREFP

    int g = lane >> 2, tq = lane & 3;
#pragma unroll
    for (int nt = 0; nt < 8; nt++) {
        int col = nt * 8 + tq * 2;
        float bb0 = sBias[col], bb1 = sBias[col + 1];
        size_t mA = (size_t)(m0 + r0 + g) * G_ + n0 + col;
        size_t mB = (size_t)(m0 + r0 + g + 8) * G_ + n0 + col;
        float2 v0 = make_float2(acc[nt][0] + bb0, acc[nt][1] + bb1);
        float2 v1 = make_float2(acc[nt][2] + bb0, acc[nt][3] + bb1);
        *(float2*)&Cout[mA] = v0;
        *(float2*)&Cout[mB] = v1;
    }
}
#define SMEM_PROJ (P_BUF * 2 * 2)

// ---------------- FUSED 2-layer LSTM recurrence (R13 structure) -------------
// 128 blocks x 512 threads, 513 fused steps. Block bid owns h0/h1 cols
// [8bid, 8bid+8). Step t: layer0 computes h0[t] (t<512) from h0[t-1];
// layer1 computes h1[t-1] (t>=1) from h0[t-1], h1[t-2].
// Warps 0-7: [W_hh0 | W_ih1] (64 gate-cols) x h0[t-1].
// Warps 8-15: W_hh1 (32 gate-cols) x h1[t-2].
// ONE syncthreads per chunk (start-of-chunk sync orders buffer reuse).
extern __shared__ char smem_dyn[];
__global__ __launch_bounds__(512) void lstm_fused(
    const float* __restrict__ xproj,
    const float* __restrict__ Whh0,
    const float* __restrict__ bih1, const float* __restrict__ bhh1)
{
    __half* sW0 = (__half*)smem_dyn;            // 32 x 1032 resident
    __half* sH0 = sW0 + 32 * 1032;              // 2 x 64x136
    __half* sH1 = sH0 + 2 * 8704;               // 2 x 64x136
    __half* sWi = sH1 + 2 * 8704;               // 2 x 32x136 (W_ih1 stream)
    __half* sW1 = sWi + 2 * 4352;               // 2 x 32x136 (W_hh1 stream)
    float* sG01 = (float*)(sW1 + 2 * 4352);     // 64 x 66
    float* sG1  = sG01 + 64 * 66;               // 64 x 34
    float* sC0  = sG1 + 64 * 34;                // 512
    float* sC1  = sC0 + 512;                    // 512
    float* sB1  = sC1 + 512;                    // 32

    int tid = threadIdx.x, w = tid >> 5, lane = tid & 31;
    int bid = blockIdx.x;
    int jbase = bid * 8;

    for (int i = tid; i < 32 * 1024; i += 512) {
        int n = i >> 10, k = i & 1023;
        float v = Whh0[(size_t)((n >> 3) * H_ + jbase + (n & 7)) * H_ + k];
        sW0[n * 1032 + k] = __float2half(v);
    }
    if (tid < 32) {
        int gr = (tid >> 3) * H_ + jbase + (tid & 7);
        sB1[tid] = bih1[gr] + bhh1[gr];
    }
    sC0[tid] = 0.f;
    sC1[tid] = 0.f;

    int isA = (w < 8);
    int w2 = isA ? w : (w - 8);
    int rowg = w2 & 3, colg = w2 >> 2;
    int r0 = rowg * 16;
    int lrA = (lane & 7) + (lane & 8);
    int lcA = (lane & 16) ? 8 : 0;
    int bRow = lane & 7;
    int bK = ((lane >> 3) & 3) * 8;

    __half* sHx = isA ? sH0 : sH1;
    uint32_t aA[2];
#pragma unroll
    for (int bf = 0; bf < 2; bf++)
        aA[bf] = cvta_s(&sHx[bf * 8704 + (r0 + lrA) * 136 + lcA]);

    uint32_t bRes[4], bStr[2][4];
#pragma unroll
    for (int ct = 0; ct < 4; ct++) {
        bRes[ct] = cvta_s(&sW0[(ct * 8 + bRow) * 1032 + bK]);
#pragma unroll
        for (int bf = 0; bf < 2; bf++)
            bStr[bf][ct] = cvta_s(&sWi[bf * 4352 + (ct * 8 + bRow) * 136 + bK]);
    }
    uint32_t bSt1[2][2];
#pragma unroll
    for (int ct = 0; ct < 2; ct++)
#pragma unroll
        for (int bf = 0; bf < 2; bf++)
            bSt1[bf][ct] = cvta_s(&sW1[bf * 4352 + (colg * 16 + ct * 8 + bRow) * 136 + bK]);

    uint32_t dH0[2], dH1[2], dWi[2], dW1[2];
#pragma unroll
    for (int bf = 0; bf < 2; bf++) {
        dH0[bf] = cvta_s(&sH0[bf * 8704]);
        dH1[bf] = cvta_s(&sH1[bf * 8704]);
        dWi[bf] = cvta_s(&sWi[bf * 4352]);
        dW1[bf] = cvta_s(&sW1[bf * 4352]);
    }
    int pr[2], ps[2];
#pragma unroll
    for (int it = 0; it < 2; it++) {
        int idx = tid + it * 512;
        pr[it] = idx >> 4;
        ps[it] = (idx & 15) * 8;
    }
    int wrow = tid >> 4;
    int wseg = (tid & 15) * 8;
    uint32_t wso = (uint32_t)(wrow * 136 + wseg) * 2u;
    size_t wgrow = (size_t)((wrow >> 3) * H_ + jbase + (wrow & 7)) * (size_t)H_;
    const __half* gWi = g_wi1h;
    const __half* gW1 = g_wh1h;

    int g = lane >> 2, tq = lane & 3;
    int bA = r0 + g, bB = bA + 8;
    int cA = colg * 32;
    int c1 = colg * 16;

    int cb = tid >> 3, cj = tid & 7;
    const float* xpb = xproj + (size_t)cb * G_ + jbase + cj;

    __syncthreads();

#define PREF(ch, bf) do {                                                     \
    int kc_ = (ch) * 128;                                                     \
    _Pragma("unroll")                                                         \
    for (int it = 0; it < 2; it++) {                                          \
        uint32_t so = (uint32_t)(pr[it] * 136 + ps[it]) * 2u;                 \
        CP_ASYNC16(dH0[(bf)] + so, hr0 + pr[it] * H_ + kc_ + ps[it]);         \
        CP_ASYNC16(dH1[(bf)] + so, hr1 + pr[it] * H_ + kc_ + ps[it]);         \
    }                                                                         \
    CP_ASYNC16(dWi[(bf)] + wso, gWi + wgrow + kc_ + wseg);                    \
    CP_ASYNC16(dW1[(bf)] + wso, gW1 + wgrow + kc_ + wseg);                    \
    CP_COMMIT();                                                              \
} while (0)

    for (int t = 0; t <= T_; t++) {
        const __half* hr0 = g_h0[(t + 1) & 1];   // h0[t-1]
        const __half* hr1 = g_h1[t & 1];         // h1[t-2]

        PREF(0, 0);

        float xg0 = 0.f, xg1 = 0.f, xg2 = 0.f, xg3 = 0.f;
        if (t < T_) {
            size_t xt = (size_t)t * B_ * G_;
            xg0 = xpb[xt];
            xg1 = xpb[xt + 1 * H_];
            xg2 = xpb[xt + 2 * H_];
            xg3 = xpb[xt + 3 * H_];
        }

        float acc[4][4];
#pragma unroll
        for (int i = 0; i < 4; i++)
#pragma unroll
            for (int j = 0; j < 4; j++) acc[i][j] = 0.f;

        for (int ch = 0; ch < 8; ch++) {
            int cur = ch & 1;
            CP_WAIT0();
            __syncthreads();   // single sync/chunk: orders buffer reuse (WAR-safe)
            if (ch < 7) PREF(ch + 1, cur ^ 1);

            int kc = ch * 128;
            if (isA) {
#pragma unroll
                for (int kg = 0; kg < 4; kg++) {
                    uint32_t koff = (uint32_t)(kg * 32) * 2u;
                    uint32_t a0[4], a1[4];
                    ldsm4(a0, aA[cur] + koff);
                    ldsm4(a1, aA[cur] + koff + 32);
#pragma unroll
                    for (int ct = 0; ct < 4; ct++) {
                        uint32_t b[4];
                        uint32_t addr = colg ? (bStr[cur][ct] + koff)
                                             : (bRes[ct] + (uint32_t)(kc + kg * 32) * 2u);
                        ldsm4(b, addr);
                        mma16816h(acc[ct], a0, b);
                        mma16816h(acc[ct], a1, b + 2);
                    }
                }
            } else {
#pragma unroll
                for (int kg = 0; kg < 4; kg++) {
                    uint32_t koff = (uint32_t)(kg * 32) * 2u;
                    uint32_t a0[4], a1[4];
                    ldsm4(a0, aA[cur] + koff);
                    ldsm4(a1, aA[cur] + koff + 32);
#pragma unroll
                    for (int ct = 0; ct < 2; ct++) {
                        uint32_t b[4];
                        ldsm4(b, bSt1[cur][ct] + koff);
                        mma16816h(acc[ct], a0, b);
                        mma16816h(acc[ct], a1, b + 2);
                    }
                }
            }
        }

        if (isA) {
#pragma unroll
            for (int ct = 0; ct < 4; ct++) {
                int col = cA + ct * 8 + tq * 2;
                *(float2*)&sG01[bA * 66 + col] = make_float2(acc[ct][0], acc[ct][1]);
                *(float2*)&sG01[bB * 66 + col] = make_float2(acc[ct][2], acc[ct][3]);
            }
        } else {
#pragma unroll
            for (int ct = 0; ct < 2; ct++) {
                int col = c1 + ct * 8 + tq * 2;
                *(float2*)&sG1[bA * 34 + col] = make_float2(acc[ct][0], acc[ct][1]);
                *(float2*)&sG1[bB * 34 + col] = make_float2(acc[ct][2], acc[ct][3]);
            }
        }
        __syncthreads();

        __half* wr0 = g_h0[t & 1];
        __half* wr1 = g_h1[(t + 1) & 1];
        if (t < T_) {
            float iv = sG01[cb * 66 + cj]      + xg0;
            float fv = sG01[cb * 66 + 8 + cj]  + xg1;
            float gv = sG01[cb * 66 + 16 + cj] + xg2;
            float ov = sG01[cb * 66 + 24 + cj] + xg3;
            float ig = fsigmoid(iv), fg = fsigmoid(fv);
            float gg = ftanh(gv), og = fsigmoid(ov);
            float cc = fg * sC0[tid] + ig * gg;
            sC0[tid] = cc;
            float hh = og * ftanh(cc);
            wr0[cb * H_ + jbase + cj] = __float2half(hh);
        }
        if (t >= 1) {
            float iv = sG01[cb * 66 + 32 + cj]      + sG1[cb * 34 + cj]      + sB1[cj];
            float fv = sG01[cb * 66 + 32 + 8 + cj]  + sG1[cb * 34 + 8 + cj]  + sB1[8 + cj];
            float gv = sG01[cb * 66 + 32 + 16 + cj] + sG1[cb * 34 + 16 + cj] + sB1[16 + cj];
            float ov = sG01[cb * 66 + 32 + 24 + cj] + sG1[cb * 34 + 24 + cj] + sB1[24 + cj];
            float ig = fsigmoid(iv), fg = fsigmoid(fv);
            float gg = ftanh(gv), og = fsigmoid(ov);
            float cc = fg * sC1[tid] + ig * gg;
            sC1[tid] = cc;
            float hh = og * ftanh(cc);
            wr1[cb * H_ + jbase + cj] = __float2half(hh);
            if (t == T_) g_hlast[cb * H_ + jbase + cj] = hh;
        }
        if (t < T_) gridbar2(t, bid);
    }
#undef PREF
}
#define SMEM_FUSED ((32*1032 + 2*8704*2 + 2*4352*2) * 2 + (64*66 + 64*34 + 512 + 512 + 32) * 4)

// ---------------- FC head ----------------
__global__ __launch_bounds__(256) void fc_kernel(
    const float* __restrict__ fc_w, const float* __restrict__ fc_b,
    float* __restrict__ out)
{
    __shared__ float sh[H_];
    int b = blockIdx.x, tid = threadIdx.x;
    const float* hlast = g_hlast + (size_t)b * H_;
    for (int i = tid; i < H_; i += 256) sh[i] = hlast[i];
    __syncthreads();
    int o = tid;
    const float* wrow = fc_w + (size_t)o * H_;
    float acc = fc_b[o];
#pragma unroll 8
    for (int k = 0; k < H_; k++) acc += sh[k] * wrow[k];
    out[b * O_ + o] = acc;
}

// ---------------- launch ----------------
extern "C" void kernel_launch(void* const* d_in, const int* in_sizes, int n_in,
                              void* d_out, int out_size) {
    (void)in_sizes; (void)n_in; (void)out_size;
    const float* x     = (const float*)d_in[0];
    const float* W_ih0 = (const float*)d_in[1];
    const float* W_hh0 = (const float*)d_in[2];
    const float* b_ih0 = (const float*)d_in[3];
    const float* b_hh0 = (const float*)d_in[4];
    const float* W_ih1 = (const float*)d_in[5];
    const float* W_hh1 = (const float*)d_in[6];
    const float* b_ih1 = (const float*)d_in[7];
    const float* b_hh1 = (const float*)d_in[8];
    const float* fc_w  = (const float*)d_in[9];
    const float* fc_b  = (const float*)d_in[10];
    float* out = (float*)d_out;

    float* xp0;
    __nv_bfloat16 *xhi, *xlo, *w0hi, *w0lo;
    __half *wi1h, *wh1h;
    cudaGetSymbolAddress((void**)&xp0, g_xproj0);
    cudaGetSymbolAddress((void**)&xhi, g_xhi);
    cudaGetSymbolAddress((void**)&xlo, g_xlo);
    cudaGetSymbolAddress((void**)&w0hi, g_wih0hi);
    cudaGetSymbolAddress((void**)&w0lo, g_wih0lo);
    cudaGetSymbolAddress((void**)&wi1h, g_wi1h);
    cudaGetSymbolAddress((void**)&wh1h, g_wh1h);

    cudaFuncSetAttribute(lstm_fused,
        cudaFuncAttributeMaxDynamicSharedMemorySize, SMEM_FUSED);
    cudaFuncSetAttribute(mma_xproj,
        cudaFuncAttributeMaxDynamicSharedMemorySize, SMEM_PROJ);

    int nx4 = B_ * T_ * I_ / 4;
    split_kernel<<<(nx4 + 255) / 256, 256>>>(x, xhi, xlo, nx4);
    int nw04 = G_ * I_ / 4;
    split_kernel<<<(nw04 + 255) / 256, 256>>>(W_ih0, w0hi, w0lo, nw04);
    int nw14 = G_ * H_ / 4;
    conv_half<<<(nw14 + 255) / 256, 256>>>(W_ih1, wi1h, nw14);
    conv_half<<<(nw14 + 255) / 256, 256>>>(W_hh1, wh1h, nw14);

    dim3 pgrid(G_ / 64, (B_ * T_) / 128);
    mma_xproj<<<pgrid, 256, SMEM_PROJ>>>(xhi, xlo, w0hi, w0lo, b_ih0, b_hh0, xp0, I_);

    init_kernel<<<64, 256>>>();
    lstm_fused<<<128, 512, SMEM_FUSED>>>(xp0, W_hh0, b_ih1, b_hh1);

    fc_kernel<<<64, 256>>>(fc_w, fc_b, out);
}